// round 5
// baseline (speedup 1.0000x reference)
#include <cuda_runtime.h>
#include <cstdint>
#include <math.h>

#define BATCH   1024
#define SEQ     96
#define INSZ    128
#define HID     1024
#define G4      4096
#define HORIZON 24
#define OUTSZ   128
#define KCAT    1152   // 1024 + 128

#define BK      32
#define SMS     36     // smem row stride in floats (conflict-free)
#define STAGES  3      // bridge/out-proj kernel
#define LSTGS   4      // step kernel stages

// ---------------------------------------------------------------------------
// Scratch (device globals; allocation is forbidden)
// ---------------------------------------------------------------------------
__device__ __align__(16) float g_h   [2 * BATCH * HID];   // encoder h ping-pong
__device__ __align__(16) float g_c   [BATCH * HID];       // encoder c (in-place)
__device__ __align__(16) float g_hcat[2 * BATCH * KCAT];  // decoder [h | out_prev] ping-pong
__device__ __align__(16) float g_cd  [BATCH * HID];       // decoder c
__device__ __align__(16) float g_We  [G4 * KCAT];         // gate-interleaved, tf32-rounded
__device__ __align__(16) float g_Wd  [G4 * KCAT];
__device__ __align__(16) float g_be  [G4];
__device__ __align__(16) float g_bd  [G4];

// ---------------------------------------------------------------------------
// Helpers
// ---------------------------------------------------------------------------
__device__ __forceinline__ float tf32_rna(float f) {
    uint32_t r; asm("cvt.rna.tf32.f32 %0, %1;" : "=r"(r) : "f"(f));
    return __uint_as_float(r);
}
__device__ __forceinline__ void mma_tf32(float* c, const uint32_t* a, const uint32_t* b) {
    asm volatile(
        "mma.sync.aligned.m16n8k8.row.col.f32.tf32.tf32.f32 "
        "{%0,%1,%2,%3}, {%4,%5,%6,%7}, {%8,%9}, {%0,%1,%2,%3};"
        : "+f"(c[0]), "+f"(c[1]), "+f"(c[2]), "+f"(c[3])
        : "r"(a[0]), "r"(a[1]), "r"(a[2]), "r"(a[3]), "r"(b[0]), "r"(b[1]));
}
__device__ __forceinline__ void cp16(float* smem, const float* g) {
    uint32_t s = (uint32_t)__cvta_generic_to_shared(smem);
    asm volatile("cp.async.cg.shared.global [%0], [%1], 16;" :: "r"(s), "l"(g));
}
__device__ __forceinline__ float fsig(float x) {
    return __fdividef(1.0f, 1.0f + __expf(-x));
}
__device__ __forceinline__ float ftanh(float x) {
    return __fdividef(2.0f, 1.0f + __expf(-2.0f * x)) - 1.0f;
}

// ---------------------------------------------------------------------------
// Weight prep (gate-interleaved concat; weights tf32-RNA-rounded so the GEMMs
// can use raw-bit truncation on activations only)
// ---------------------------------------------------------------------------
__global__ void prep_w(const float* __restrict__ Whh, const float* __restrict__ Wih,
                       const float* __restrict__ b1, const float* __restrict__ b2,
                       float* __restrict__ Wcat, float* __restrict__ bcat)
{
    long idx = (long)blockIdx.x * blockDim.x + threadIdx.x;
    if (idx >= (long)G4 * KCAT) return;
    int row = (int)(idx / KCAT);
    int k   = (int)(idx % KCAT);
    int j = row >> 2, g = row & 3;
    int orow = g * HID + j;
    float w = (k < HID) ? Whh[(size_t)orow * HID + k]
                        : Wih[(size_t)orow * INSZ + (k - HID)];
    Wcat[idx] = tf32_rna(w);
    if (k == 0) bcat[row] = b1[orow] + b2[orow];
}

// ---------------------------------------------------------------------------
// Fused LSTM step kernel: CTA tile 128x256, 8 warps, warp tile 32x128.
// 4-stage cp.async pipeline, ONE __syncthreads per K-chunk.
// K chunks [cb, ce): chunk < 32 reads A1 (lda1); chunk >= 32 reads A2 (k-1024).
// Gate-interleaved cols (c = 4j+g). LSTM epilogue via shfl partner.
// ---------------------------------------------------------------------------
__global__ void __launch_bounds__(256, 1)
lstm_step(const float* __restrict__ A1, int lda1,
          const float* __restrict__ A2, int lda2,
          const float* __restrict__ B,  int ldb,
          const float* __restrict__ bias,
          float* __restrict__ H, int ldh,
          float* __restrict__ C, int ldc,
          int cb, int ce, int first)
{
    constexpr int AS_ST = 128 * SMS;
    constexpr int BS_ST = 256 * SMS;

    extern __shared__ float sm[];
    float* As = sm;                   // [LSTGS][128][SMS]
    float* Bs = sm + LSTGS * AS_ST;   // [LSTGS][256][SMS]

    const int tid  = threadIdx.x;
    const int lane = tid & 31;
    const int wid  = tid >> 5;
    const int wm   = wid & 3;         // 4 warps along M (32 rows each)
    const int wn   = wid >> 2;        // 2 warps along N (128 cols each)
    const int lr   = lane >> 2;
    const int lc   = lane & 3;
    const int m0   = blockIdx.y * 128;
    const int n0   = blockIdx.x * 256;

    float acc[2][16][4];
    #pragma unroll
    for (int mi = 0; mi < 2; mi++)
        #pragma unroll
        for (int nf = 0; nf < 16; nf++)
            #pragma unroll
            for (int t = 0; t < 4; t++) acc[mi][nf][t] = 0.0f;

    auto load_stage = [&](int st, int chunk) {
        float* as = As + st * AS_ST;
        float* bs = Bs + st * BS_ST;
        const int k0 = chunk * BK;
        #pragma unroll
        for (int i = 0; i < 4; i++) {           // A: 128 rows * 8 f4 / 256 thr
            int q = tid + i * 256;
            int r = q >> 3, c4 = q & 7;
            const float* src = (chunk < 32)
                ? A1 + (size_t)(m0 + r) * lda1 + k0 + c4 * 4
                : A2 + (size_t)(m0 + r) * lda2 + (k0 - HID) + c4 * 4;
            cp16(as + r * SMS + c4 * 4, src);
        }
        #pragma unroll
        for (int i = 0; i < 8; i++) {           // B: 256 rows * 8 f4 / 256 thr
            int q = tid + i * 256;
            int r = q >> 3, c4 = q & 7;
            cp16(bs + r * SMS + c4 * 4,
                 B + (size_t)(n0 + r) * ldb + k0 + c4 * 4);
        }
    };

    // Prologue: chunks cb, cb+1
    load_stage(0, cb);
    asm volatile("cp.async.commit_group;");
    if (cb + 1 < ce) load_stage(1, cb + 1);
    asm volatile("cp.async.commit_group;");

    for (int ch = cb; ch < ce; ch++) {
        const int it = ch - cb;
        asm volatile("cp.async.wait_group 1;");
        __syncthreads();
        // Load into stage (it+2)%4: last read at iter it-2; all warps passed
        // the sync at iter it-1 after that read -> safe with a single sync.
        if (ch + 2 < ce) load_stage((it + 2) & (LSTGS - 1), ch + 2);
        asm volatile("cp.async.commit_group;");

        const int st = it & (LSTGS - 1);
        const float* as = As + st * AS_ST + (wm * 32) * SMS;
        const float* bs = Bs + st * BS_ST + (wn * 128) * SMS;
        #pragma unroll
        for (int ks = 0; ks < 4; ks++) {
            const int kk = ks * 8;
            uint32_t af[2][4];
            #pragma unroll
            for (int mi = 0; mi < 2; mi++) {
                const float* ap = as + (mi * 16 + lr) * SMS + kk + lc;
                af[mi][0] = __float_as_uint(ap[0]);
                af[mi][1] = __float_as_uint(ap[8 * SMS]);
                af[mi][2] = __float_as_uint(ap[4]);
                af[mi][3] = __float_as_uint(ap[8 * SMS + 4]);
            }
            #pragma unroll
            for (int nf = 0; nf < 16; nf++) {
                const float* bp = bs + (nf * 8 + lr) * SMS + kk + lc;
                uint32_t bf[2];
                bf[0] = __float_as_uint(bp[0]);
                bf[1] = __float_as_uint(bp[4]);
                #pragma unroll
                for (int mi = 0; mi < 2; mi++)
                    mma_tf32(acc[mi][nf], af[mi], bf);
            }
        }
    }

    // -------- LSTM epilogue --------
    const int rb = m0 + wm * 32 + lr;
    #pragma unroll
    for (int mi = 0; mi < 2; mi++) {
        #pragma unroll
        for (int nf = 0; nf < 16; nf++) {
            int cg = n0 + wn * 128 + nf * 8 + 2 * lc;   // = 4j+g (even)
            float v0 = acc[mi][nf][0] + bias[cg];
            float v1 = acc[mi][nf][1] + bias[cg + 1];
            float v2 = acc[mi][nf][2] + bias[cg];
            float v3 = acc[mi][nf][3] + bias[cg + 1];
            float p0 = __shfl_xor_sync(0xffffffffu, v0, 1);
            float p1 = __shfl_xor_sync(0xffffffffu, v1, 1);
            float p2 = __shfl_xor_sync(0xffffffffu, v2, 1);
            float p3 = __shfl_xor_sync(0xffffffffu, v3, 1);
            if ((lane & 1) == 0) {
                // this lane holds (i,f); partner holds (g~,o)
                int j  = cg >> 2;
                int r0 = rb + mi * 16, r1 = r0 + 8;
                {
                    float i_ = fsig(v0), f_ = fsig(v1);
                    float g_ = ftanh(p0), o_ = fsig(p1);
                    float co = first ? 0.0f : C[(size_t)r0 * ldc + j];
                    float cn = f_ * co + i_ * g_;
                    C[(size_t)r0 * ldc + j] = cn;
                    H[(size_t)r0 * ldh + j] = o_ * ftanh(cn);
                }
                {
                    float i_ = fsig(v2), f_ = fsig(v3);
                    float g_ = ftanh(p2), o_ = fsig(p3);
                    float co = first ? 0.0f : C[(size_t)r1 * ldc + j];
                    float cn = f_ * co + i_ * g_;
                    C[(size_t)r1 * ldc + j] = cn;
                    H[(size_t)r1 * ldh + j] = o_ * ftanh(cn);
                }
            }
        }
    }
}

// ---------------------------------------------------------------------------
// mma.sync GEMM for bridge / out-projection (round-3 proven, LSTM-free)
// ---------------------------------------------------------------------------
template<int TBM, int BN>
__global__ void __launch_bounds__((TBM / 32) * (BN / 64) * 32)
gemm_k(const float* __restrict__ A1, int lda1,
       const float* __restrict__ B,  int ldb,
       const float* __restrict__ bias,
       float* __restrict__ O1, int ldo1,
       float* __restrict__ O2, int ldo2,
       int cb, int ce)
{
    constexpr int WM = TBM / 32;
    constexpr int WN = BN / 64;
    constexpr int NT = WM * WN * 32;
    constexpr int AS_ST = TBM * SMS;
    constexpr int BS_ST = BN * SMS;
    constexpr int IA = TBM * 8 / NT;
    constexpr int IB = BN * 8 / NT;

    extern __shared__ float smf[];
    float* As = smf;
    float* Bs = smf + STAGES * AS_ST;

    const int tid  = threadIdx.x;
    const int lane = tid & 31;
    const int wid  = tid >> 5;
    const int wm   = wid % WM;
    const int wn   = wid / WM;
    const int lr   = lane >> 2;
    const int lc   = lane & 3;
    const int m0   = blockIdx.y * TBM;
    const int n0   = blockIdx.x * BN;

    float acc[2][8][4];
    #pragma unroll
    for (int mi = 0; mi < 2; mi++)
        #pragma unroll
        for (int nf = 0; nf < 8; nf++)
            #pragma unroll
            for (int t = 0; t < 4; t++) acc[mi][nf][t] = 0.0f;

    auto load_stage = [&](int st, int chunk) {
        float* as = As + st * AS_ST;
        float* bs = Bs + st * BS_ST;
        const int k0 = chunk * BK;
        #pragma unroll
        for (int i = 0; i < IA; i++) {
            int q = tid + i * NT;
            int r = q >> 3, c4 = q & 7;
            cp16(as + r * SMS + c4 * 4, A1 + (size_t)(m0 + r) * lda1 + k0 + c4 * 4);
        }
        #pragma unroll
        for (int i = 0; i < IB; i++) {
            int q = tid + i * NT;
            int r = q >> 3, c4 = q & 7;
            cp16(bs + r * SMS + c4 * 4, B + (size_t)(n0 + r) * ldb + k0 + c4 * 4);
        }
    };

    load_stage(0, cb);
    asm volatile("cp.async.commit_group;");
    if (cb + 1 < ce) load_stage(1, cb + 1);
    asm volatile("cp.async.commit_group;");

    for (int ch = cb; ch < ce; ch++) {
        const int it = ch - cb;
        asm volatile("cp.async.wait_group 1;");
        __syncthreads();
        if (ch + 2 < ce) load_stage((it + 2) % STAGES, ch + 2);
        asm volatile("cp.async.commit_group;");

        const int st = it % STAGES;
        const float* as = As + st * AS_ST + (wm * 32) * SMS;
        const float* bs = Bs + st * BS_ST + (wn * 64) * SMS;
        #pragma unroll
        for (int ks = 0; ks < 4; ks++) {
            const int kk = ks * 8;
            uint32_t af[2][4];
            #pragma unroll
            for (int mi = 0; mi < 2; mi++) {
                const float* ap = as + (mi * 16 + lr) * SMS + kk + lc;
                af[mi][0] = __float_as_uint(ap[0]);
                af[mi][1] = __float_as_uint(ap[8 * SMS]);
                af[mi][2] = __float_as_uint(ap[4]);
                af[mi][3] = __float_as_uint(ap[8 * SMS + 4]);
            }
            #pragma unroll
            for (int nf = 0; nf < 8; nf++) {
                const float* bp = bs + (nf * 8 + lr) * SMS + kk + lc;
                uint32_t bf[2];
                bf[0] = __float_as_uint(bp[0]);
                bf[1] = __float_as_uint(bp[4]);
                #pragma unroll
                for (int mi = 0; mi < 2; mi++)
                    mma_tf32(acc[mi][nf], af[mi], bf);
            }
        }
        __syncthreads();
    }

    const int rb = m0 + wm * 32 + lr;
    #pragma unroll
    for (int mi = 0; mi < 2; mi++) {
        #pragma unroll
        for (int nf = 0; nf < 8; nf++) {
            int cg = n0 + wn * 64 + nf * 8 + 2 * lc;
            float b0 = bias ? bias[cg] : 0.0f;
            float b1 = bias ? bias[cg + 1] : 0.0f;
            int r0 = rb + mi * 16, r1 = r0 + 8;
            float2 v0 = make_float2(acc[mi][nf][0] + b0, acc[mi][nf][1] + b1);
            float2 v1 = make_float2(acc[mi][nf][2] + b0, acc[mi][nf][3] + b1);
            *(float2*)&O1[(size_t)r0 * ldo1 + cg] = v0;
            *(float2*)&O1[(size_t)r1 * ldo1 + cg] = v1;
            if (O2) {
                *(float2*)&O2[(size_t)r0 * ldo2 + cg] = v0;
                *(float2*)&O2[(size_t)r1 * ldo2 + cg] = v1;
            }
        }
    }
}

// ---------------------------------------------------------------------------
// Launch sequence (graph-capturable: kernel launches only)
// ---------------------------------------------------------------------------
extern "C" void kernel_launch(void* const* d_in, const int* in_sizes, int n_in,
                              void* d_out, int out_size)
{
    const float* x      = (const float*)d_in[0];
    const float* W_ih_e = (const float*)d_in[1];
    const float* W_hh_e = (const float*)d_in[2];
    const float* b_ih_e = (const float*)d_in[3];
    const float* b_hh_e = (const float*)d_in[4];
    const float* W_ih_d = (const float*)d_in[5];
    const float* W_hh_d = (const float*)d_in[6];
    const float* b_ih_d = (const float*)d_in[7];
    const float* b_hh_d = (const float*)d_in[8];
    const float* W_fc   = (const float*)d_in[9];
    const float* b_fc   = (const float*)d_in[10];
    const float* W_fcc  = (const float*)d_in[11];
    const float* b_fcc  = (const float*)d_in[12];
    const float* W_out  = (const float*)d_in[13];
    const float* b_out  = (const float*)d_in[14];
    float* out = (float*)d_out;

    float *h, *c, *hcat, *cd, *We, *Wd, *be, *bd;
    cudaGetSymbolAddress((void**)&h,    g_h);
    cudaGetSymbolAddress((void**)&c,    g_c);
    cudaGetSymbolAddress((void**)&hcat, g_hcat);
    cudaGetSymbolAddress((void**)&cd,   g_cd);
    cudaGetSymbolAddress((void**)&We,   g_We);
    cudaGetSymbolAddress((void**)&Wd,   g_Wd);
    cudaGetSymbolAddress((void**)&be,   g_be);
    cudaGetSymbolAddress((void**)&bd,   g_bd);

    const int SMEM_L = LSTGS * (128 + 256) * SMS * 4;   // 221,184 B
    const int SMEM_B = STAGES * (128 + 128) * SMS * 4;  // 110,592 B
    const int SMEM_O = STAGES * (64 + 128) * SMS * 4;   //  82,944 B
    cudaFuncSetAttribute(lstm_step,        cudaFuncAttributeMaxDynamicSharedMemorySize, SMEM_L);
    cudaFuncSetAttribute(gemm_k<128, 128>, cudaFuncAttributeMaxDynamicSharedMemorySize, SMEM_B);
    cudaFuncSetAttribute(gemm_k<64, 128>,  cudaFuncAttributeMaxDynamicSharedMemorySize, SMEM_O);

    // ---- weight prep ----
    {
        long total = (long)G4 * KCAT;
        int blocks = (int)((total + 255) / 256);
        prep_w<<<blocks, 256>>>(W_hh_e, W_ih_e, b_ih_e, b_hh_e, We, be);
        prep_w<<<blocks, 256>>>(W_hh_d, W_ih_d, b_ih_d, b_hh_d, Wd, bd);
    }

    const dim3 gL(G4 / 256, BATCH / 128);   // (16, 8) — 128 CTAs
    const dim3 gB(HID / 128, BATCH / 128);  // (8, 8)
    const dim3 gO(OUTSZ / 128, BATCH / 64); // (1, 16)

    // ---- encoder: 96 fused steps ----
    int p = 0;
    for (int t = 0; t < SEQ; t++) {
        lstm_step<<<gL, 256, SMEM_L>>>(
            h + (size_t)p * BATCH * HID, HID,
            x + (size_t)t * INSZ, SEQ * INSZ,
            We, KCAT, be,
            h + (size_t)(1 - p) * BATCH * HID, HID,
            c, HID,
            (t == 0) ? 32 : 0, 36, (t == 0) ? 1 : 0);
        p ^= 1;
    }
    float* h_fin = h + (size_t)p * BATCH * HID;

    // ---- bridge ----
    float* hc0 = hcat;
    float* hc1 = hcat + (size_t)BATCH * KCAT;
    gemm_k<128, 128><<<gB, 256, SMEM_B>>>(
        h_fin, HID, W_fc, HID, b_fc, hc0, KCAT, nullptr, 0, 0, 32);
    gemm_k<128, 128><<<gB, 256, SMEM_B>>>(
        h_fin, HID, W_fcc, HID, b_fcc, cd, HID, nullptr, 0, 0, 32);

    // ---- decoder: 24 steps ----
    int q = 0;
    for (int t = 0; t < HORIZON; t++) {
        float* src = (q == 0) ? hc0 : hc1;
        float* dst = (q == 0) ? hc1 : hc0;
        lstm_step<<<gL, 256, SMEM_L>>>(
            src, KCAT, src + HID, KCAT,
            Wd, KCAT, bd,
            dst, KCAT,
            cd, HID,
            0, (t == 0) ? 32 : 36, 0);
        gemm_k<64, 128><<<gO, 128, SMEM_O>>>(
            dst, KCAT, W_out, HID, b_out,
            out + (size_t)t * OUTSZ, HORIZON * OUTSZ,
            dst + HID, KCAT, 0, 32);
        q ^= 1;
    }
}

// round 6
// speedup vs baseline: 1.1776x; 1.1776x over previous
#include <cuda_runtime.h>
#include <cstdint>
#include <math.h>

#define BATCH   1024
#define SEQ     96
#define INSZ    128
#define HID     1024
#define G4      4096
#define HORIZON 24
#define OUTSZ   128
#define KCAT    1152   // 1024 + 128

#define BK      32
#define SMS     36     // smem row stride in floats; 144B rows -> LDSM conflict-free
#define STAGES  3

// ---------------------------------------------------------------------------
// Scratch (device globals; allocation is forbidden)
// ---------------------------------------------------------------------------
__device__ __align__(16) float g_h   [2 * BATCH * HID];
__device__ __align__(16) float g_c   [BATCH * HID];
__device__ __align__(16) float g_hcat[2 * BATCH * KCAT];
__device__ __align__(16) float g_cd  [BATCH * HID];
__device__ __align__(16) float g_We  [G4 * KCAT];
__device__ __align__(16) float g_Wd  [G4 * KCAT];
__device__ __align__(16) float g_be  [G4];
__device__ __align__(16) float g_bd  [G4];

// ---------------------------------------------------------------------------
// Helpers
// ---------------------------------------------------------------------------
__device__ __forceinline__ float tf32_rna(float f) {
    uint32_t r; asm("cvt.rna.tf32.f32 %0, %1;" : "=r"(r) : "f"(f));
    return __uint_as_float(r);
}
__device__ __forceinline__ void mma_tf32(float* c, const uint32_t* a, const uint32_t* b) {
    asm volatile(
        "mma.sync.aligned.m16n8k8.row.col.f32.tf32.tf32.f32 "
        "{%0,%1,%2,%3}, {%4,%5,%6,%7}, {%8,%9}, {%0,%1,%2,%3};"
        : "+f"(c[0]), "+f"(c[1]), "+f"(c[2]), "+f"(c[3])
        : "r"(a[0]), "r"(a[1]), "r"(a[2]), "r"(a[3]), "r"(b[0]), "r"(b[1]));
}
__device__ __forceinline__ void ldsm4(uint32_t* r, uint32_t saddr) {
    asm volatile("ldmatrix.sync.aligned.m8n8.x4.shared.b16 {%0,%1,%2,%3}, [%4];"
        : "=r"(r[0]), "=r"(r[1]), "=r"(r[2]), "=r"(r[3]) : "r"(saddr));
}
__device__ __forceinline__ void cp16(float* smem, const float* g) {
    uint32_t s = (uint32_t)__cvta_generic_to_shared(smem);
    asm volatile("cp.async.cg.shared.global [%0], [%1], 16;" :: "r"(s), "l"(g));
}
__device__ __forceinline__ uint32_t smem_u32(const void* p) {
    return (uint32_t)__cvta_generic_to_shared(p);
}
__device__ __forceinline__ float fsig(float x) {
    return __fdividef(1.0f, 1.0f + __expf(-x));
}
__device__ __forceinline__ float ftanh(float x) {
    return __fdividef(2.0f, 1.0f + __expf(-2.0f * x)) - 1.0f;
}

// ---------------------------------------------------------------------------
// Weight prep (gate-interleaved concat; weights tf32-RNA-rounded so the GEMMs
// can use raw-bit truncation on activations only)
// ---------------------------------------------------------------------------
__global__ void prep_w(const float* __restrict__ Whh, const float* __restrict__ Wih,
                       const float* __restrict__ b1, const float* __restrict__ b2,
                       float* __restrict__ Wcat, float* __restrict__ bcat)
{
    long idx = (long)blockIdx.x * blockDim.x + threadIdx.x;
    if (idx >= (long)G4 * KCAT) return;
    int row = (int)(idx / KCAT);
    int k   = (int)(idx % KCAT);
    int j = row >> 2, g = row & 3;
    int orow = g * HID + j;
    float w = (k < HID) ? Whh[(size_t)orow * HID + k]
                        : Wih[(size_t)orow * INSZ + (k - HID)];
    Wcat[idx] = tf32_rna(w);
    if (k == 0) bcat[row] = b1[orow] + b2[orow];
}

// ---------------------------------------------------------------------------
// Core GEMM: C[M, N] = Acat @ B^T (tf32 truncation, fp32 accum).
// 3-stage cp.async pipeline, ONE __syncthreads per K-chunk, ldmatrix fragment
// loads. Warp tile 32x64. K chunks [cb, ce): chunk < 32 reads A1 (lda1);
// chunk >= 32 reads A2 at k-1024 (lda2).
// LSTM=true: gate-interleaved cols (c = 4j+g); shfl-partner epilogue writes
// h into O1 and updates c in O2. LSTM=false: bias epilogue (+optional O2 copy).
// ---------------------------------------------------------------------------
template<int TBM, int BN, bool LSTM>
__global__ void __launch_bounds__((TBM / 32) * (BN / 64) * 32)
gemm_k(const float* __restrict__ A1, int lda1,
       const float* __restrict__ A2, int lda2,
       const float* __restrict__ B,  int ldb,
       const float* __restrict__ bias,
       float* __restrict__ O1, int ldo1,
       float* __restrict__ O2, int ldo2,
       int cb, int ce, int first)
{
    constexpr int WM = TBM / 32;
    constexpr int WN = BN / 64;
    constexpr int NT = WM * WN * 32;
    constexpr int AS_ST = TBM * SMS;
    constexpr int BS_ST = BN * SMS;
    constexpr int IA = TBM * 8 / NT;
    constexpr int IB = BN * 8 / NT;

    extern __shared__ float sm[];
    float* As = sm;
    float* Bs = sm + STAGES * AS_ST;

    const int tid  = threadIdx.x;
    const int lane = tid & 31;
    const int wid  = tid >> 5;
    const int wm   = wid % WM;
    const int wn   = wid / WM;
    const int lr   = lane >> 2;
    const int lc   = lane & 3;
    const int m0   = blockIdx.y * TBM;
    const int n0   = blockIdx.x * BN;

    // ldmatrix lane->row/col mapping (see header comment in round notes):
    // A x4 tiles: (rows 0-7,klo)(rows 8-15,klo)(rows 0-7,khi)(rows 8-15,khi)
    const int a_row = lane & 15;
    const int a_col = (lane >> 4) << 2;
    // B x4 tiles: (n 0-7,klo)(n 0-7,khi)(n 8-15,klo)(n 8-15,khi)
    const int b_row = ((lane >> 4) << 3) + (lane & 7);
    const int b_col = ((lane >> 3) & 1) << 2;

    float acc[2][8][4];
    #pragma unroll
    for (int mi = 0; mi < 2; mi++)
        #pragma unroll
        for (int nf = 0; nf < 8; nf++)
            #pragma unroll
            for (int t = 0; t < 4; t++) acc[mi][nf][t] = 0.0f;

    auto load_stage = [&](int st, int chunk) {
        float* as = As + st * AS_ST;
        float* bs = Bs + st * BS_ST;
        const int k0 = chunk * BK;
        #pragma unroll
        for (int i = 0; i < IA; i++) {
            int q = tid + i * NT;
            int r = q >> 3, c4 = q & 7;
            const float* src = (chunk < 32)
                ? A1 + (size_t)(m0 + r) * lda1 + k0 + c4 * 4
                : A2 + (size_t)(m0 + r) * lda2 + (k0 - HID) + c4 * 4;
            cp16(as + r * SMS + c4 * 4, src);
        }
        #pragma unroll
        for (int i = 0; i < IB; i++) {
            int q = tid + i * NT;
            int r = q >> 3, c4 = q & 7;
            cp16(bs + r * SMS + c4 * 4, B + (size_t)(n0 + r) * ldb + k0 + c4 * 4);
        }
    };

    load_stage(0, cb);
    asm volatile("cp.async.commit_group;");
    if (cb + 1 < ce) load_stage(1, cb + 1);
    asm volatile("cp.async.commit_group;");

    for (int ch = cb; ch < ce; ch++) {
        const int it = ch - cb;
        asm volatile("cp.async.wait_group 1;");
        __syncthreads();
        // Stage (it+2)%3 == (it-1)%3 was last read before the sync above.
        if (ch + 2 < ce) load_stage((it + 2) % STAGES, ch + 2);
        asm volatile("cp.async.commit_group;");

        const int st = it % STAGES;
        const uint32_t as_u = smem_u32(As + st * AS_ST + (wm * 32) * SMS);
        const uint32_t bs_u = smem_u32(Bs + st * BS_ST + (wn * 64) * SMS);
        #pragma unroll
        for (int ks = 0; ks < 4; ks++) {
            const int kk = ks * 8;
            uint32_t af[2][4];
            #pragma unroll
            for (int mi = 0; mi < 2; mi++)
                ldsm4(af[mi], as_u + (uint32_t)(((mi * 16 + a_row) * SMS + kk + a_col) * 4));
            #pragma unroll
            for (int nfp = 0; nfp < 4; nfp++) {
                uint32_t bf4[4];
                ldsm4(bf4, bs_u + (uint32_t)(((nfp * 16 + b_row) * SMS + kk + b_col) * 4));
                #pragma unroll
                for (int mi = 0; mi < 2; mi++) {
                    mma_tf32(acc[mi][nfp * 2],     af[mi], &bf4[0]);
                    mma_tf32(acc[mi][nfp * 2 + 1], af[mi], &bf4[2]);
                }
            }
        }
    }

    const int rb = m0 + wm * 32 + lr;
    if (!LSTM) {
        #pragma unroll
        for (int mi = 0; mi < 2; mi++) {
            #pragma unroll
            for (int nf = 0; nf < 8; nf++) {
                int cg = n0 + wn * 64 + nf * 8 + 2 * lc;
                float b0 = bias ? bias[cg] : 0.0f;
                float b1 = bias ? bias[cg + 1] : 0.0f;
                int r0 = rb + mi * 16, r1 = r0 + 8;
                float2 v0 = make_float2(acc[mi][nf][0] + b0, acc[mi][nf][1] + b1);
                float2 v1 = make_float2(acc[mi][nf][2] + b0, acc[mi][nf][3] + b1);
                *(float2*)&O1[(size_t)r0 * ldo1 + cg] = v0;
                *(float2*)&O1[(size_t)r1 * ldo1 + cg] = v1;
                if (O2) {
                    *(float2*)&O2[(size_t)r0 * ldo2 + cg] = v0;
                    *(float2*)&O2[(size_t)r1 * ldo2 + cg] = v1;
                }
            }
        }
    } else {
        #pragma unroll
        for (int mi = 0; mi < 2; mi++) {
            #pragma unroll
            for (int nf = 0; nf < 8; nf++) {
                int cg = n0 + wn * 64 + nf * 8 + 2 * lc;   // = 4j+g (even)
                float v0 = acc[mi][nf][0] + bias[cg];
                float v1 = acc[mi][nf][1] + bias[cg + 1];
                float v2 = acc[mi][nf][2] + bias[cg];
                float v3 = acc[mi][nf][3] + bias[cg + 1];
                float p0 = __shfl_xor_sync(0xffffffffu, v0, 1);
                float p1 = __shfl_xor_sync(0xffffffffu, v1, 1);
                float p2 = __shfl_xor_sync(0xffffffffu, v2, 1);
                float p3 = __shfl_xor_sync(0xffffffffu, v3, 1);
                if ((lane & 1) == 0) {
                    int j  = cg >> 2;
                    int r0 = rb + mi * 16, r1 = r0 + 8;
                    {
                        float i_ = fsig(v0), f_ = fsig(v1);
                        float g_ = ftanh(p0), o_ = fsig(p1);
                        float co = first ? 0.0f : O2[(size_t)r0 * ldo2 + j];
                        float cn = f_ * co + i_ * g_;
                        O2[(size_t)r0 * ldo2 + j] = cn;
                        O1[(size_t)r0 * ldo1 + j] = o_ * ftanh(cn);
                    }
                    {
                        float i_ = fsig(v2), f_ = fsig(v3);
                        float g_ = ftanh(p2), o_ = fsig(p3);
                        float co = first ? 0.0f : O2[(size_t)r1 * ldo2 + j];
                        float cn = f_ * co + i_ * g_;
                        O2[(size_t)r1 * ldo2 + j] = cn;
                        O1[(size_t)r1 * ldo1 + j] = o_ * ftanh(cn);
                    }
                }
            }
        }
    }
}

// ---------------------------------------------------------------------------
// Launch sequence (graph-capturable: kernel launches only)
// ---------------------------------------------------------------------------
extern "C" void kernel_launch(void* const* d_in, const int* in_sizes, int n_in,
                              void* d_out, int out_size)
{
    const float* x      = (const float*)d_in[0];
    const float* W_ih_e = (const float*)d_in[1];
    const float* W_hh_e = (const float*)d_in[2];
    const float* b_ih_e = (const float*)d_in[3];
    const float* b_hh_e = (const float*)d_in[4];
    const float* W_ih_d = (const float*)d_in[5];
    const float* W_hh_d = (const float*)d_in[6];
    const float* b_ih_d = (const float*)d_in[7];
    const float* b_hh_d = (const float*)d_in[8];
    const float* W_fc   = (const float*)d_in[9];
    const float* b_fc   = (const float*)d_in[10];
    const float* W_fcc  = (const float*)d_in[11];
    const float* b_fcc  = (const float*)d_in[12];
    const float* W_out  = (const float*)d_in[13];
    const float* b_out  = (const float*)d_in[14];
    float* out = (float*)d_out;

    float *h, *c, *hcat, *cd, *We, *Wd, *be, *bd;
    cudaGetSymbolAddress((void**)&h,    g_h);
    cudaGetSymbolAddress((void**)&c,    g_c);
    cudaGetSymbolAddress((void**)&hcat, g_hcat);
    cudaGetSymbolAddress((void**)&cd,   g_cd);
    cudaGetSymbolAddress((void**)&We,   g_We);
    cudaGetSymbolAddress((void**)&Wd,   g_Wd);
    cudaGetSymbolAddress((void**)&be,   g_be);
    cudaGetSymbolAddress((void**)&bd,   g_bd);

    const int SMEM_L = STAGES * (128 + 256) * SMS * 4;  // 165,888 B
    const int SMEM_B = STAGES * (128 + 128) * SMS * 4;  // 110,592 B
    const int SMEM_O = STAGES * (64 + 128) * SMS * 4;   //  82,944 B
    cudaFuncSetAttribute(gemm_k<128, 256, true>,  cudaFuncAttributeMaxDynamicSharedMemorySize, SMEM_L);
    cudaFuncSetAttribute(gemm_k<128, 128, false>, cudaFuncAttributeMaxDynamicSharedMemorySize, SMEM_B);
    cudaFuncSetAttribute(gemm_k<64, 128, false>,  cudaFuncAttributeMaxDynamicSharedMemorySize, SMEM_O);

    // ---- weight prep ----
    {
        long total = (long)G4 * KCAT;
        int blocks = (int)((total + 255) / 256);
        prep_w<<<blocks, 256>>>(W_hh_e, W_ih_e, b_ih_e, b_hh_e, We, be);
        prep_w<<<blocks, 256>>>(W_hh_d, W_ih_d, b_ih_d, b_hh_d, Wd, bd);
    }

    const dim3 gL(G4 / 256, BATCH / 128);   // (16, 8) — 128 CTAs
    const dim3 gB(HID / 128, BATCH / 128);  // (8, 8)
    const dim3 gO(OUTSZ / 128, BATCH / 64); // (1, 16)

    // ---- encoder: 96 fused GEMM+LSTM steps ----
    int p = 0;
    for (int t = 0; t < SEQ; t++) {
        gemm_k<128, 256, true><<<gL, 512, SMEM_L>>>(
            h + (size_t)p * BATCH * HID, HID,
            x + (size_t)t * INSZ, SEQ * INSZ,
            We, KCAT, be,
            h + (size_t)(1 - p) * BATCH * HID, HID,
            c, HID,
            (t == 0) ? 32 : 0, 36, (t == 0) ? 1 : 0);
        p ^= 1;
    }
    float* h_fin = h + (size_t)p * BATCH * HID;

    // ---- bridge ----
    float* hc0 = hcat;
    float* hc1 = hcat + (size_t)BATCH * KCAT;
    gemm_k<128, 128, false><<<gB, 256, SMEM_B>>>(
        h_fin, HID, nullptr, 0, W_fc, HID, b_fc,
        hc0, KCAT, nullptr, 0, 0, 32, 0);
    gemm_k<128, 128, false><<<gB, 256, SMEM_B>>>(
        h_fin, HID, nullptr, 0, W_fcc, HID, b_fcc,
        cd, HID, nullptr, 0, 0, 32, 0);

    // ---- decoder: 24 steps ----
    int q = 0;
    for (int t = 0; t < HORIZON; t++) {
        float* src = (q == 0) ? hc0 : hc1;
        float* dst = (q == 0) ? hc1 : hc0;
        gemm_k<128, 256, true><<<gL, 512, SMEM_L>>>(
            src, KCAT, src + HID, KCAT,
            Wd, KCAT, bd,
            dst, KCAT,
            cd, HID,
            0, (t == 0) ? 32 : 36, 0);
        gemm_k<64, 128, false><<<gO, 128, SMEM_O>>>(
            dst, KCAT, nullptr, 0, W_out, HID, b_out,
            out + (size_t)t * OUTSZ, HORIZON * OUTSZ,
            dst + HID, KCAT, 0, 32, 0);
        q ^= 1;
    }
}

// round 8
// speedup vs baseline: 1.9109x; 1.6226x over previous
#include <cuda_runtime.h>
#include <cuda_fp16.h>
#include <cstdint>
#include <math.h>

#define BATCH   1024
#define SEQ     96
#define INSZ    128
#define HID     1024
#define G4      4096
#define HORIZON 24
#define OUTSZ   128
#define KCAT    1152   // 1024 + 128

#define CK      64     // K elements per chunk (halves)
#define HCH     16     // chunks covering the h part (1024/64)
#define SMS_H   72     // smem row stride in halves (144B rows; ldmatrix conflict-free)
#define STAGES  3

// ---------------------------------------------------------------------------
// Scratch (device globals; allocation is forbidden)
// ---------------------------------------------------------------------------
__device__ __align__(16) __half g_h   [2 * BATCH * HID];    // encoder h ping-pong (fp16)
__device__ __align__(16) float  g_c   [BATCH * HID];        // encoder c (fp32)
__device__ __align__(16) __half g_hcat[2 * BATCH * KCAT];   // decoder [h | out_prev] ping-pong
__device__ __align__(16) float  g_cd  [BATCH * HID];        // decoder c
__device__ __align__(16) __half g_xh  [BATCH * SEQ * INSZ]; // x converted to fp16
__device__ __align__(16) __half g_We  [G4 * KCAT];          // gate-interleaved [W_hh_e|W_ih_e]
__device__ __align__(16) __half g_Wd  [G4 * KCAT];
__device__ __align__(16) __half g_Wfc [HID * HID];
__device__ __align__(16) __half g_Wfcc[HID * HID];
__device__ __align__(16) __half g_Wout[OUTSZ * HID];
__device__ __align__(16) float  g_be  [G4];
__device__ __align__(16) float  g_bd  [G4];

// ---------------------------------------------------------------------------
// Helpers
// ---------------------------------------------------------------------------
__device__ __forceinline__ void mma_f16(float* c, const uint32_t* a, const uint32_t* b) {
    asm volatile(
        "mma.sync.aligned.m16n8k16.row.col.f32.f16.f16.f32 "
        "{%0,%1,%2,%3}, {%4,%5,%6,%7}, {%8,%9}, {%0,%1,%2,%3};"
        : "+f"(c[0]), "+f"(c[1]), "+f"(c[2]), "+f"(c[3])
        : "r"(a[0]), "r"(a[1]), "r"(a[2]), "r"(a[3]), "r"(b[0]), "r"(b[1]));
}
__device__ __forceinline__ void ldsm4(uint32_t* r, uint32_t saddr) {
    asm volatile("ldmatrix.sync.aligned.m8n8.x4.shared.b16 {%0,%1,%2,%3}, [%4];"
        : "=r"(r[0]), "=r"(r[1]), "=r"(r[2]), "=r"(r[3]) : "r"(saddr));
}
__device__ __forceinline__ void cp16h(__half* smem, const __half* g) {
    uint32_t s = (uint32_t)__cvta_generic_to_shared(smem);
    asm volatile("cp.async.cg.shared.global [%0], [%1], 16;" :: "r"(s), "l"(g));
}
__device__ __forceinline__ uint32_t smem_u32(const void* p) {
    return (uint32_t)__cvta_generic_to_shared(p);
}
__device__ __forceinline__ float fsig(float x) {
    return __fdividef(1.0f, 1.0f + __expf(-x));
}
__device__ __forceinline__ float ftanh(float x) {
    return __fdividef(2.0f, 1.0f + __expf(-2.0f * x)) - 1.0f;
}
__device__ __forceinline__ void store2(float* p, float a, float b) {
    *(float2*)p = make_float2(a, b);
}
__device__ __forceinline__ void store2(__half* p, float a, float b) {
    *(__half2*)p = __floats2half2_rn(a, b);
}

// ---------------------------------------------------------------------------
// Prep kernels
// ---------------------------------------------------------------------------
__global__ void prep_w(const float* __restrict__ Whh, const float* __restrict__ Wih,
                       const float* __restrict__ b1, const float* __restrict__ b2,
                       __half* __restrict__ Wcat, float* __restrict__ bcat)
{
    long idx = (long)blockIdx.x * blockDim.x + threadIdx.x;
    if (idx >= (long)G4 * KCAT) return;
    int row = (int)(idx / KCAT);
    int k   = (int)(idx % KCAT);
    int j = row >> 2, g = row & 3;
    int orow = g * HID + j;
    float w = (k < HID) ? Whh[(size_t)orow * HID + k]
                        : Wih[(size_t)orow * INSZ + (k - HID)];
    Wcat[idx] = __float2half_rn(w);
    if (k == 0) bcat[row] = b1[orow] + b2[orow];
}

__global__ void f2h(const float* __restrict__ src, __half* __restrict__ dst, long n)
{
    long i = (long)blockIdx.x * blockDim.x + threadIdx.x;
    if (i < n) dst[i] = __float2half_rn(src[i]);
}

// ---------------------------------------------------------------------------
// Core GEMM: C[M, N] = Acat @ B^T (fp16 operands, fp32 accum).
// 3-stage cp.async pipeline, ONE __syncthreads per K-chunk, ldmatrix loads.
// Warp tile 32x64. K chunks [cb, ce) of 64 halves: chunk < HCH reads A1 (lda1);
// chunk >= HCH reads A2 at k-1024 (lda2).
// LSTM=true: gate-interleaved cols (c = 4j+g); shfl-partner epilogue writes
// fp16 h into O1 and fp32 c into O2.
// ---------------------------------------------------------------------------
template<int TBM, int BN, bool LSTM, typename T1, typename T2>
__global__ void __launch_bounds__((TBM / 32) * (BN / 64) * 32)
gemm_h(const __half* __restrict__ A1, int lda1,
       const __half* __restrict__ A2, int lda2,
       const __half* __restrict__ B,  int ldb,
       const float* __restrict__ bias,
       T1* __restrict__ O1, int ldo1,
       T2* __restrict__ O2, int ldo2,
       int cb, int ce, int first)
{
    constexpr int WM = TBM / 32;
    constexpr int WN = BN / 64;
    constexpr int NT = WM * WN * 32;
    constexpr int AS_ST = TBM * SMS_H;   // halves
    constexpr int BS_ST = BN * SMS_H;
    constexpr int IA = TBM * 8 / NT;     // 16B granules (8 halves) per thread
    constexpr int IB = BN * 8 / NT;

    extern __shared__ __half smh[];
    __half* As = smh;
    __half* Bs = smh + STAGES * AS_ST;

    const int tid  = threadIdx.x;
    const int lane = tid & 31;
    const int wid  = tid >> 5;
    const int wm   = wid % WM;
    const int wn   = wid / WM;
    const int lr   = lane >> 2;
    const int lc   = lane & 3;
    const int m0   = blockIdx.y * TBM;
    const int n0   = blockIdx.x * BN;

    // ldmatrix lane->tile mapping (b16, non-trans):
    // A x4 tiles (m16 x k16): (m0-7,klo)(m8-15,klo)(m0-7,khi)(m8-15,khi)
    const int a_row  = lane & 15;
    const int a_koff = (lane >> 4) << 3;     // 0 or 8 halves
    // B x4 tiles (n16 x k16): (n0-7,klo)(n0-7,khi)(n8-15,klo)(n8-15,khi)
    const int b_row  = ((lane >> 4) << 3) + (lane & 7);
    const int b_koff = ((lane >> 3) & 1) << 3;

    float acc[2][8][4];
    #pragma unroll
    for (int mi = 0; mi < 2; mi++)
        #pragma unroll
        for (int nf = 0; nf < 8; nf++)
            #pragma unroll
            for (int t = 0; t < 4; t++) acc[mi][nf][t] = 0.0f;

    auto load_stage = [&](int st, int chunk) {
        __half* as = As + st * AS_ST;
        __half* bs = Bs + st * BS_ST;
        const int k0 = chunk * CK;
        #pragma unroll
        for (int i = 0; i < IA; i++) {
            int q = tid + i * NT;
            int r = q >> 3, c8 = (q & 7) * 8;
            const __half* src = (chunk < HCH)
                ? A1 + (size_t)(m0 + r) * lda1 + k0 + c8
                : A2 + (size_t)(m0 + r) * lda2 + (k0 - HID) + c8;
            cp16h(as + r * SMS_H + c8, src);
        }
        #pragma unroll
        for (int i = 0; i < IB; i++) {
            int q = tid + i * NT;
            int r = q >> 3, c8 = (q & 7) * 8;
            cp16h(bs + r * SMS_H + c8, B + (size_t)(n0 + r) * ldb + k0 + c8);
        }
    };

    load_stage(0, cb);
    asm volatile("cp.async.commit_group;");
    if (cb + 1 < ce) load_stage(1, cb + 1);
    asm volatile("cp.async.commit_group;");

    for (int ch = cb; ch < ce; ch++) {
        const int it = ch - cb;
        asm volatile("cp.async.wait_group 1;");
        __syncthreads();
        // Stage (it+2)%3 == (it-1)%3 was last read before the sync above.
        if (ch + 2 < ce) load_stage((it + 2) % STAGES, ch + 2);
        asm volatile("cp.async.commit_group;");

        const int st = it % STAGES;
        const uint32_t as_u = smem_u32(As + st * AS_ST + (wm * 32) * SMS_H);
        const uint32_t bs_u = smem_u32(Bs + st * BS_ST + (wn * 64) * SMS_H);
        #pragma unroll
        for (int ks = 0; ks < 4; ks++) {           // 4 x k16 = chunk of 64
            const int kk = ks * 16;
            uint32_t af[2][4];
            #pragma unroll
            for (int mi = 0; mi < 2; mi++)
                ldsm4(af[mi], as_u + (uint32_t)(((mi * 16 + a_row) * SMS_H + kk + a_koff) * 2));
            #pragma unroll
            for (int nfp = 0; nfp < 4; nfp++) {
                uint32_t bf4[4];
                ldsm4(bf4, bs_u + (uint32_t)(((nfp * 16 + b_row) * SMS_H + kk + b_koff) * 2));
                #pragma unroll
                for (int mi = 0; mi < 2; mi++) {
                    mma_f16(acc[mi][nfp * 2],     af[mi], &bf4[0]);
                    mma_f16(acc[mi][nfp * 2 + 1], af[mi], &bf4[2]);
                }
            }
        }
    }

    const int rb = m0 + wm * 32 + lr;
    if (!LSTM) {
        #pragma unroll
        for (int mi = 0; mi < 2; mi++) {
            #pragma unroll
            for (int nf = 0; nf < 8; nf++) {
                int cg = n0 + wn * 64 + nf * 8 + 2 * lc;
                float b0 = bias ? bias[cg] : 0.0f;
                float b1 = bias ? bias[cg + 1] : 0.0f;
                int r0 = rb + mi * 16, r1 = r0 + 8;
                store2(&O1[(size_t)r0 * ldo1 + cg], acc[mi][nf][0] + b0, acc[mi][nf][1] + b1);
                store2(&O1[(size_t)r1 * ldo1 + cg], acc[mi][nf][2] + b0, acc[mi][nf][3] + b1);
                if (O2) {
                    store2(&O2[(size_t)r0 * ldo2 + cg], acc[mi][nf][0] + b0, acc[mi][nf][1] + b1);
                    store2(&O2[(size_t)r1 * ldo2 + cg], acc[mi][nf][2] + b0, acc[mi][nf][3] + b1);
                }
            }
        }
    } else {
        #pragma unroll
        for (int mi = 0; mi < 2; mi++) {
            #pragma unroll
            for (int nf = 0; nf < 8; nf++) {
                int cg = n0 + wn * 64 + nf * 8 + 2 * lc;   // = 4j+g (even)
                float v0 = acc[mi][nf][0] + bias[cg];
                float v1 = acc[mi][nf][1] + bias[cg + 1];
                float v2 = acc[mi][nf][2] + bias[cg];
                float v3 = acc[mi][nf][3] + bias[cg + 1];
                float p0 = __shfl_xor_sync(0xffffffffu, v0, 1);
                float p1 = __shfl_xor_sync(0xffffffffu, v1, 1);
                float p2 = __shfl_xor_sync(0xffffffffu, v2, 1);
                float p3 = __shfl_xor_sync(0xffffffffu, v3, 1);
                if ((lane & 1) == 0) {
                    int j  = cg >> 2;
                    int r0 = rb + mi * 16, r1 = r0 + 8;
                    {
                        float i_ = fsig(v0), f_ = fsig(v1);
                        float g_ = ftanh(p0), o_ = fsig(p1);
                        float co = first ? 0.0f : ((const float*)O2)[(size_t)r0 * ldo2 + j];
                        float cn = f_ * co + i_ * g_;
                        ((float*)O2)[(size_t)r0 * ldo2 + j] = cn;
                        ((__half*)O1)[(size_t)r0 * ldo1 + j] = __float2half_rn(o_ * ftanh(cn));
                    }
                    {
                        float i_ = fsig(v2), f_ = fsig(v3);
                        float g_ = ftanh(p2), o_ = fsig(p3);
                        float co = first ? 0.0f : ((const float*)O2)[(size_t)r1 * ldo2 + j];
                        float cn = f_ * co + i_ * g_;
                        ((float*)O2)[(size_t)r1 * ldo2 + j] = cn;
                        ((__half*)O1)[(size_t)r1 * ldo1 + j] = __float2half_rn(o_ * ftanh(cn));
                    }
                }
            }
        }
    }
}

// ---------------------------------------------------------------------------
// Launch sequence (graph-capturable: kernel launches only)
// ---------------------------------------------------------------------------
extern "C" void kernel_launch(void* const* d_in, const int* in_sizes, int n_in,
                              void* d_out, int out_size)
{
    const float* x      = (const float*)d_in[0];
    const float* W_ih_e = (const float*)d_in[1];
    const float* W_hh_e = (const float*)d_in[2];
    const float* b_ih_e = (const float*)d_in[3];
    const float* b_hh_e = (const float*)d_in[4];
    const float* W_ih_d = (const float*)d_in[5];
    const float* W_hh_d = (const float*)d_in[6];
    const float* b_ih_d = (const float*)d_in[7];
    const float* b_hh_d = (const float*)d_in[8];
    const float* W_fc   = (const float*)d_in[9];
    const float* b_fc   = (const float*)d_in[10];
    const float* W_fcc  = (const float*)d_in[11];
    const float* b_fcc  = (const float*)d_in[12];
    const float* W_out  = (const float*)d_in[13];
    const float* b_out  = (const float*)d_in[14];
    float* out = (float*)d_out;

    __half *h, *hcat, *xh, *We, *Wd, *Wfc, *Wfcc, *Wout;
    float *c, *cd, *be, *bd;
    cudaGetSymbolAddress((void**)&h,    g_h);
    cudaGetSymbolAddress((void**)&c,    g_c);
    cudaGetSymbolAddress((void**)&hcat, g_hcat);
    cudaGetSymbolAddress((void**)&cd,   g_cd);
    cudaGetSymbolAddress((void**)&xh,   g_xh);
    cudaGetSymbolAddress((void**)&We,   g_We);
    cudaGetSymbolAddress((void**)&Wd,   g_Wd);
    cudaGetSymbolAddress((void**)&Wfc,  g_Wfc);
    cudaGetSymbolAddress((void**)&Wfcc, g_Wfcc);
    cudaGetSymbolAddress((void**)&Wout, g_Wout);
    cudaGetSymbolAddress((void**)&be,   g_be);
    cudaGetSymbolAddress((void**)&bd,   g_bd);

    const int SMEM_L = STAGES * (128 + 256) * SMS_H * 2;  // 82,944 B
    const int SMEM_B = STAGES * (128 + 128) * SMS_H * 2;  // 55,296 B
    const int SMEM_O = STAGES * (64 + 128) * SMS_H * 2;   // 41,472 B
    cudaFuncSetAttribute((const void*)gemm_h<128, 256, true, __half, float>,
                         cudaFuncAttributeMaxDynamicSharedMemorySize, SMEM_L);
    cudaFuncSetAttribute((const void*)gemm_h<128, 128, false, __half, float>,
                         cudaFuncAttributeMaxDynamicSharedMemorySize, SMEM_B);
    cudaFuncSetAttribute((const void*)gemm_h<128, 128, false, float, float>,
                         cudaFuncAttributeMaxDynamicSharedMemorySize, SMEM_B);
    cudaFuncSetAttribute((const void*)gemm_h<64, 128, false, float, __half>,
                         cudaFuncAttributeMaxDynamicSharedMemorySize, SMEM_O);

    // ---- prep: weights + x to fp16 ----
    {
        long total = (long)G4 * KCAT;
        int blocks = (int)((total + 255) / 256);
        prep_w<<<blocks, 256>>>(W_hh_e, W_ih_e, b_ih_e, b_hh_e, We, be);
        prep_w<<<blocks, 256>>>(W_hh_d, W_ih_d, b_ih_d, b_hh_d, Wd, bd);
        long nx = (long)BATCH * SEQ * INSZ;
        f2h<<<(int)((nx + 255) / 256), 256>>>(x, xh, nx);
        long nw = (long)HID * HID;
        f2h<<<(int)((nw + 255) / 256), 256>>>(W_fc,  Wfc,  nw);
        f2h<<<(int)((nw + 255) / 256), 256>>>(W_fcc, Wfcc, nw);
        long no = (long)OUTSZ * HID;
        f2h<<<(int)((no + 255) / 256), 256>>>(W_out, Wout, no);
    }

    const dim3 gL(G4 / 256, BATCH / 128);   // (16, 8) — 128 CTAs
    const dim3 gB(HID / 128, BATCH / 128);  // (8, 8)
    const dim3 gO(OUTSZ / 128, BATCH / 64); // (1, 16)

    // ---- encoder: 96 fused GEMM+LSTM steps ----
    int p = 0;
    for (int t = 0; t < SEQ; t++) {
        gemm_h<128, 256, true, __half, float><<<gL, 512, SMEM_L>>>(
            h + (size_t)p * BATCH * HID, HID,
            xh + (size_t)t * INSZ, SEQ * INSZ,
            We, KCAT, be,
            h + (size_t)(1 - p) * BATCH * HID, HID,
            c, HID,
            (t == 0) ? HCH : 0, 18, (t == 0) ? 1 : 0);
        p ^= 1;
    }
    __half* h_fin = h + (size_t)p * BATCH * HID;

    // ---- bridge ----
    __half* hc0 = hcat;
    __half* hc1 = hcat + (size_t)BATCH * KCAT;
    gemm_h<128, 128, false, __half, float><<<gB, 256, SMEM_B>>>(
        h_fin, HID, (const __half*)nullptr, 0, Wfc, HID, b_fc,
        hc0, KCAT, (float*)nullptr, 0, 0, HCH, 0);
    gemm_h<128, 128, false, float, float><<<gB, 256, SMEM_B>>>(
        h_fin, HID, (const __half*)nullptr, 0, Wfcc, HID, b_fcc,
        cd, HID, (float*)nullptr, 0, 0, HCH, 0);

    // ---- decoder: 24 steps ----
    int q = 0;
    for (int t = 0; t < HORIZON; t++) {
        __half* src = (q == 0) ? hc0 : hc1;
        __half* dst = (q == 0) ? hc1 : hc0;
        gemm_h<128, 256, true, __half, float><<<gL, 512, SMEM_L>>>(
            src, KCAT, src + HID, KCAT,
            Wd, KCAT, bd,
            dst, KCAT,
            cd, HID,
            0, (t == 0) ? HCH : 18, 0);
        gemm_h<64, 128, false, float, __half><<<gO, 128, SMEM_O>>>(
            dst, KCAT, (const __half*)nullptr, 0, Wout, HID, b_out,
            out + (size_t)t * OUTSZ, HORIZON * OUTSZ,
            dst + HID, KCAT, 0, HCH, 0);
        q ^= 1;
    }
}